// round 10
// baseline (speedup 1.0000x reference)
#include <cuda_runtime.h>
#include <math.h>

// SenseEmbedding -- converged champion (measured 16.864us, tied-best of 10 variants).
//
//  x:   [16384, 12] int32   -- [w0, w1, ctx0..ctx9]
//  W_g: [100000, 128] f32
//  W_s: [100000, 8, 128] f32
//  out: [16384, 1] f32
//
// Design facts (all measured on GB300 across rounds 1-9):
//  * One warp per row; lane = float4 slice -> every embedding gather is one
//    fully coalesced 512B access.
//  * W_s loaded with __ldcs (evict-first): keeps the W_g table L2-resident.
//    This was the only 2x+ lever (39.7us -> 16.9us). Hint-based evict_last
//    policies regress (no persisting-L2 carveout available under harness).
//  * Persistent single-wave grid (148 SMs x 4 blocks); performance is
//    occupancy-invariant (84%/45%/43% all tie), confirming an L2/LTS
//    transit bound (~221MB compulsory flow per pass ~= LTS cap).
//  * TMA bulk-copy of W_s and L1-bypass of W_g were tried: no gain.

#define CTX 10
#define NUM_SENSES 8
#define VEC4 32   // 128 floats = 32 float4

#define NBLOCKS 592   // 148 SMs * 4 resident blocks: exactly one wave
#define NTHREADS 256  // 8 warps/block

__global__ void __launch_bounds__(NTHREADS, 4)
sense_embedding_kernel(const int4* __restrict__ x4,
                       const float4* __restrict__ Wg,
                       const float4* __restrict__ Ws,
                       float* __restrict__ out,
                       int batch)
{
    int warp0 = (blockIdx.x * NTHREADS + threadIdx.x) >> 5;
    int lane = threadIdx.x & 31;
    const int warp_stride = (NBLOCKS * NTHREADS) >> 5;   // 4736 warps total

    for (int row = warp0; row < batch; row += warp_stride) {
        // x row = 12 ints = 3 x int4 (warp-uniform broadcast loads)
        const int4* xr = x4 + (size_t)row * 3;
        int4 xa = __ldg(&xr[0]);
        int4 xb = __ldg(&xr[1]);
        int4 xc = __ldg(&xr[2]);
        int w0 = xa.x, w1 = xa.y;
        int toks[CTX] = { xa.z, xa.w, xb.x, xb.y, xb.z,
                          xb.w, xc.x, xc.y, xc.z, xc.w };

        // ---- independent gathers: target + 8 senses + 10 context rows ----
        float4 tv = __ldg(&Wg[(size_t)w1 * VEC4 + lane]);   // target row

        const float4* ws_row = Ws + (size_t)w0 * (NUM_SENSES * VEC4) + lane;
        float4 v[NUM_SENSES];
#pragma unroll
        for (int s = 0; s < NUM_SENSES; s++)
            v[s] = __ldcs(&ws_row[s * VEC4]);               // evict-first stream

        float4 acc = make_float4(0.f, 0.f, 0.f, 0.f);
#pragma unroll
        for (int i = 0; i < CTX; i++) {
            float4 cv = __ldg(&Wg[(size_t)toks[i] * VEC4 + lane]);
            acc.x += cv.x; acc.y += cv.y; acc.z += cv.z; acc.w += cv.w;
        }

        // ---- per-lane partial dots ----
        float partial[NUM_SENSES];
#pragma unroll
        for (int s = 0; s < NUM_SENSES; s++)
            partial[s] = v[s].x * acc.x + v[s].y * acc.y
                       + v[s].z * acc.z + v[s].w * acc.w;

        // ---- warp-reduce each score; argmax (first max wins, jnp.argmax) ----
        float best = -INFINITY;
        int bestk = 0;
#pragma unroll
        for (int s = 0; s < NUM_SENSES; s++) {
            float p = partial[s];
            p += __shfl_xor_sync(0xffffffffu, p, 16);
            p += __shfl_xor_sync(0xffffffffu, p, 8);
            p += __shfl_xor_sync(0xffffffffu, p, 4);
            p += __shfl_xor_sync(0xffffffffu, p, 2);
            p += __shfl_xor_sync(0xffffffffu, p, 1);
            if (p > best) { best = p; bestk = s; }  // warp-uniform
        }

        // ---- chosen sense already in registers; select + final dot ----
        float4 ch = v[0];
#pragma unroll
        for (int s = 1; s < NUM_SENSES; s++)
            if (s == bestk) ch = v[s];

        float d = ch.x * tv.x + ch.y * tv.y + ch.z * tv.z + ch.w * tv.w;
        d += __shfl_xor_sync(0xffffffffu, d, 16);
        d += __shfl_xor_sync(0xffffffffu, d, 8);
        d += __shfl_xor_sync(0xffffffffu, d, 4);
        d += __shfl_xor_sync(0xffffffffu, d, 2);
        d += __shfl_xor_sync(0xffffffffu, d, 1);

        if (lane == 0)
            out[row] = 1.0f / (1.0f + __expf(-d));
    }
}

extern "C" void kernel_launch(void* const* d_in, const int* in_sizes, int n_in,
                              void* d_out, int out_size)
{
    const int4*   x  = (const int4*)d_in[0];
    const float4* Wg = (const float4*)d_in[1];
    const float4* Ws = (const float4*)d_in[2];
    float* out = (float*)d_out;

    int batch = in_sizes[0] / (2 + CTX);   // 16384
    sense_embedding_kernel<<<NBLOCKS, NTHREADS>>>(x, Wg, Ws, out, batch);
}

// round 11
// speedup vs baseline: 1.0152x; 1.0152x over previous
#include <cuda_runtime.h>
#include <math.h>

// SenseEmbedding -- converged champion (16.864us, best measurement; 6 variants
// tie within run-to-run noise of +-0.3us).
//
//  x:   [16384, 12] int32   -- [w0, w1, ctx0..ctx9]
//  W_g: [100000, 128] f32
//  W_s: [100000, 8, 128] f32
//  out: [16384, 1] f32
//
// Measured design facts (GB300, rounds 1-10):
//  * One warp per row; lane = float4 slice -> every embedding gather is one
//    fully coalesced 512B access.
//  * W_s via __ldcs (evict-first): protects W_g's L2 residency. Only 2x+
//    lever found (39.7us -> 16.9us). evict_last hint policies regress (no
//    persisting-L2 carveout permitted under the harness).
//  * Persistent single-wave grid (148 SMs x 4 blocks). Performance is
//    invariant to occupancy (84%/45%/43%), wave count, L1 policy, and
//    TMA-vs-LDG path -> bound by compulsory L2/LTS byte transit
//    (~221MB/pass incl. structural W_s DRAM refill; 160MB stream > 126MB L2).

#define CTX 10
#define NUM_SENSES 8
#define VEC4 32   // 128 floats = 32 float4

#define NBLOCKS 592   // 148 SMs * 4 resident blocks: exactly one wave
#define NTHREADS 256  // 8 warps/block

__global__ void __launch_bounds__(NTHREADS, 4)
sense_embedding_kernel(const int4* __restrict__ x4,
                       const float4* __restrict__ Wg,
                       const float4* __restrict__ Ws,
                       float* __restrict__ out,
                       int batch)
{
    int warp0 = (blockIdx.x * NTHREADS + threadIdx.x) >> 5;
    int lane = threadIdx.x & 31;
    const int warp_stride = (NBLOCKS * NTHREADS) >> 5;   // 4736 warps total

    for (int row = warp0; row < batch; row += warp_stride) {
        // x row = 12 ints = 3 x int4 (warp-uniform broadcast loads)
        const int4* xr = x4 + (size_t)row * 3;
        int4 xa = __ldg(&xr[0]);
        int4 xb = __ldg(&xr[1]);
        int4 xc = __ldg(&xr[2]);
        int w0 = xa.x, w1 = xa.y;
        int toks[CTX] = { xa.z, xa.w, xb.x, xb.y, xb.z,
                          xb.w, xc.x, xc.y, xc.z, xc.w };

        // ---- independent gathers: target + 8 senses + 10 context rows ----
        float4 tv = __ldg(&Wg[(size_t)w1 * VEC4 + lane]);   // target row

        const float4* ws_row = Ws + (size_t)w0 * (NUM_SENSES * VEC4) + lane;
        float4 v[NUM_SENSES];
#pragma unroll
        for (int s = 0; s < NUM_SENSES; s++)
            v[s] = __ldcs(&ws_row[s * VEC4]);               // evict-first stream

        float4 acc = make_float4(0.f, 0.f, 0.f, 0.f);
#pragma unroll
        for (int i = 0; i < CTX; i++) {
            float4 cv = __ldg(&Wg[(size_t)toks[i] * VEC4 + lane]);
            acc.x += cv.x; acc.y += cv.y; acc.z += cv.z; acc.w += cv.w;
        }

        // ---- per-lane partial dots ----
        float partial[NUM_SENSES];
#pragma unroll
        for (int s = 0; s < NUM_SENSES; s++)
            partial[s] = v[s].x * acc.x + v[s].y * acc.y
                       + v[s].z * acc.z + v[s].w * acc.w;

        // ---- warp-reduce each score; argmax (first max wins, jnp.argmax) ----
        float best = -INFINITY;
        int bestk = 0;
#pragma unroll
        for (int s = 0; s < NUM_SENSES; s++) {
            float p = partial[s];
            p += __shfl_xor_sync(0xffffffffu, p, 16);
            p += __shfl_xor_sync(0xffffffffu, p, 8);
            p += __shfl_xor_sync(0xffffffffu, p, 4);
            p += __shfl_xor_sync(0xffffffffu, p, 2);
            p += __shfl_xor_sync(0xffffffffu, p, 1);
            if (p > best) { best = p; bestk = s; }  // warp-uniform
        }

        // ---- chosen sense already in registers; select + final dot ----
        float4 ch = v[0];
#pragma unroll
        for (int s = 1; s < NUM_SENSES; s++)
            if (s == bestk) ch = v[s];

        float d = ch.x * tv.x + ch.y * tv.y + ch.z * tv.z + ch.w * tv.w;
        d += __shfl_xor_sync(0xffffffffu, d, 16);
        d += __shfl_xor_sync(0xffffffffu, d, 8);
        d += __shfl_xor_sync(0xffffffffu, d, 4);
        d += __shfl_xor_sync(0xffffffffu, d, 2);
        d += __shfl_xor_sync(0xffffffffu, d, 1);

        if (lane == 0)
            out[row] = 1.0f / (1.0f + __expf(-d));
    }
}

extern "C" void kernel_launch(void* const* d_in, const int* in_sizes, int n_in,
                              void* d_out, int out_size)
{
    const int4*   x  = (const int4*)d_in[0];
    const float4* Wg = (const float4*)d_in[1];
    const float4* Ws = (const float4*)d_in[2];
    float* out = (float*)d_out;

    int batch = in_sizes[0] / (2 + CTX);   // 16384
    sense_embedding_kernel<<<NBLOCKS, NTHREADS>>>(x, Wg, Ws, out, batch);
}